// round 7
// baseline (speedup 1.0000x reference)
#include <cuda_runtime.h>
#include <math.h>

#define NQ 8
#define NS 256          // 2^8 amplitudes
#define DEPTH 200
#define BSZ 16384
#define NXF 64
#define NT 32           // batches per block in main kernel
#define NTP 33          // padded batch stride in shared
#define NBLK (BSZ/NT)   // 512 blocks

typedef unsigned long long ull;

// ---------------- device globals (no cudaMalloc allowed) ----------------
__device__ float4 g_uv[600 * 8];     // per layer/qubit: (u.re,u.im,v.re,v.im) of RY(b)*RX(a)
__device__ float2 g_encphi[128];     // (cos(phi/2), sin(phi/2)) for encode phi angles
__device__ float2 g_v0[NS];          // U1 |0>
__device__ float2 g_S[4][NS * NS];   // segment columns: [s][c*256+m]; s:0=U2s1,1=U2s2,2=U3s1,3=U3s2
__device__ float  g_Wr[2][NS * NS];  // Re(U'[m][k]) stored [k*256+m]   (0=U2', 1=U3')
__device__ float  g_Wi[2][NS * NS];  // Im
__device__ float  g_Wn[2][NS * NS];  // -Im

// ---------------- packed f32x2 helpers ----------------
__device__ __forceinline__ void ffma2(ull& d, ull a, ull b) {
    asm("fma.rn.f32x2 %0, %1, %2, %0;" : "+l"(d) : "l"(a), "l"(b));
}
__device__ __forceinline__ ull pack2(float lo, float hi) {
    ull r; asm("mov.b64 %0, {%1, %2};" : "=l"(r) : "f"(lo), "f"(hi)); return r;
}
__device__ __forceinline__ float2 unpack2(ull v) {
    float2 r; asm("mov.b64 {%0, %1}, %2;" : "=f"(r.x), "=f"(r.y) : "l"(v)); return r;
}

// ring-CZ parity sign for amplitude index n (qubit i <-> bit 7-i)
__device__ __forceinline__ float czsign(int n) {
    int par = __popc(n & (n >> 1)) + ((n & (n >> 7)) & 1);
    return (par & 1) ? -1.0f : 1.0f;
}

// ---------------- K0: angle tables ----------------
__global__ void k_tables(const float* __restrict__ phi) {
    int tid = blockIdx.x * blockDim.x + threadIdx.x;
    int stride = gridDim.x * blockDim.x;
    for (int idx = tid; idx < 600 * 8; idx += stride) {
        int L = idx >> 3, q = idx & 7;
        int base, l;
        if (L < 200)      { base = 0;    l = L; }
        else if (L < 400) { base = 3264; l = L - 200; }
        else              { base = 6528; l = L - 400; }
        float a = phi[base + l * 16 + q];
        float b = phi[base + l * 16 + 8 + q];
        float ca, sa, cb, sb;
        sincosf(0.5f * a, &sa, &ca);
        sincosf(0.5f * b, &sb, &cb);
        g_uv[idx] = make_float4(ca * cb, sa * sb, ca * sb, -sa * cb);
    }
    for (int idx = tid; idx < 128; idx += stride) {
        int base = (idx < 64) ? 3200 : 6400;
        float p = phi[base + idx];
        float c, s;
        sincosf(0.5f * p, &s, &c);
        g_encphi[idx] = make_float2(c, s);
    }
}

// ---------------- segment layer step (register/shuffle state machine) ----------------
__device__ __forceinline__ void seg_step(float2 amp[8], const float4 uvL[8],
                                         const float sgn[8], int lane, bool docz) {
    // lane-bit gates: q = 0..4  (amp bit p = 7-q lives in lane bit p-3)
    #pragma unroll
    for (int q = 0; q < 5; q++) {
        float4 uv = uvL[q];
        int b = 4 - q;
        int mybit = (lane >> b) & 1;
        float mai = mybit ? -uv.y : uv.y;
        float mbr = mybit ?  uv.z : -uv.z;
        ull Ap = pack2(uv.x, mai),  An = pack2(-mai, uv.x);
        ull Bp = pack2(mbr, uv.w),  Bn = pack2(-uv.w, mbr);
        #pragma unroll
        for (int j = 0; j < 8; j++) {
            float pr = __shfl_xor_sync(0xffffffffu, amp[j].x, 1 << b);
            float pi = __shfl_xor_sync(0xffffffffu, amp[j].y, 1 << b);
            ull acc = 0ull;
            ffma2(acc, pack2(amp[j].x, amp[j].x), Ap);
            ffma2(acc, pack2(amp[j].y, amp[j].y), An);
            ffma2(acc, pack2(pr, pr), Bp);
            ffma2(acc, pack2(pi, pi), Bn);
            amp[j] = unpack2(acc);
        }
    }
    // local gates: q = 5,6,7 (bit p = 2,1,0 within the 8 local amps)
    #pragma unroll
    for (int q = 5; q < 8; q++) {
        float4 uv = uvL[q];
        int p = 7 - q;
        ull A00p = pack2( uv.x,  uv.y), A00n = pack2(-uv.y,  uv.x);
        ull A01p = pack2(-uv.z,  uv.w), A01n = pack2(-uv.w, -uv.z);
        ull A10p = pack2( uv.z,  uv.w), A10n = pack2(-uv.w,  uv.z);
        ull A11p = pack2( uv.x, -uv.y), A11n = pack2( uv.y,  uv.x);
        #pragma unroll
        for (int t = 0; t < 4; t++) {
            int lowm = (1 << p) - 1;
            int j0 = ((t & ~lowm) << 1) | (t & lowm);
            int j1 = j0 | (1 << p);
            float2 a0 = amp[j0], a1 = amp[j1];
            ull sx0 = pack2(a0.x, a0.x), sy0 = pack2(a0.y, a0.y);
            ull sx1 = pack2(a1.x, a1.x), sy1 = pack2(a1.y, a1.y);
            ull acc0 = 0ull, acc1 = 0ull;
            ffma2(acc0, sx0, A00p); ffma2(acc0, sy0, A00n);
            ffma2(acc0, sx1, A01p); ffma2(acc0, sy1, A01n);
            ffma2(acc1, sx0, A10p); ffma2(acc1, sy0, A10n);
            ffma2(acc1, sx1, A11p); ffma2(acc1, sy1, A11n);
            amp[j0] = unpack2(acc0);
            amp[j1] = unpack2(acc1);
        }
    }
    if (docz) {
        #pragma unroll
        for (int j = 0; j < 8; j++) { amp[j].x *= sgn[j]; amp[j].y *= sgn[j]; }
    }
}

// ---------------- K1: build segment columns + v0 ----------------
// warps 0..1023: segment s = gw>>8 (100 layers each), column gw&255.
// warp 1024 (alone in block 128): v0 over full 200 layers of block 1.
__global__ void __launch_bounds__(256) k_build() {
    int gw = blockIdx.x * 8 + (threadIdx.x >> 5);
    if (gw >= 1025) return;
    int lane = threadIdx.x & 31;

    int Lbase, NL, col;
    bool czlast;
    float2* outp;
    float initv;
    if (gw < 1024) {
        int s = gw >> 8;
        col = gw & 255;
        Lbase = 200 + s * 100;        // s=0:200, 1:300, 2:400, 3:500
        NL = 100;
        czlast = (s != 3);            // only U3-seg2's final layer has no CZ
        outp = &g_S[s][col * NS];
        initv = (s == 0 || s == 2) ? czsign(col) : 1.0f;  // fold encode-Dcz into seg1 init
    } else {
        Lbase = 0; NL = DEPTH; czlast = true; col = 0; outp = g_v0; initv = 1.0f;
    }

    float2 amp[8];
    float  sgn[8];
    #pragma unroll
    for (int j = 0; j < 8; j++) {
        int n = lane * 8 + j;
        amp[j] = (n == col) ? make_float2(initv, 0.f) : make_float2(0.f, 0.f);
        sgn[j] = czsign(n);
    }

    float4 uvA[8], uvB[8];
    #pragma unroll
    for (int q = 0; q < 8; q++) uvA[q] = g_uv[Lbase * 8 + q];

    for (int l = 0; l < NL; l += 2) {
        #pragma unroll
        for (int q = 0; q < 8; q++) uvB[q] = g_uv[(Lbase + l + 1) * 8 + q];
        seg_step(amp, uvA, sgn, lane, (l < NL - 1) || czlast);
        if (l + 2 < NL) {
            #pragma unroll
            for (int q = 0; q < 8; q++) uvA[q] = g_uv[(Lbase + l + 2) * 8 + q];
        }
        seg_step(amp, uvB, sgn, lane, (l + 1 < NL - 1) || czlast);
    }

    float4* o4 = reinterpret_cast<float4*>(outp);
    #pragma unroll
    for (int jj = 0; jj < 4; jj++)
        o4[lane * 4 + jj] = make_float4(amp[2 * jj].x, amp[2 * jj].y,
                                        amp[2 * jj + 1].x, amp[2 * jj + 1].y);
}

// ---------------- K1b: combine segments  U' = S2 * S1  -> re/im/-im planes ----------------
// block (g, cb): computes columns cb*32..+31 of U'(g), writes plane layout [k][m].
__global__ void __launch_bounds__(256) k_comb() {
    extern __shared__ float smraw[];
    float2* sPsi = (float2*)smraw;            // NS * NTP
    float2* sA2  = sPsi + NS * NTP;           // 2 x 2048 ping-pong

    int tid = threadIdx.x, lane = tid & 31, warp = tid >> 5;
    int g = blockIdx.x >> 3;
    int cbase = (blockIdx.x & 7) * 32;
    const float2* __restrict__ S1 = g_S[2 * g];
    const float2* __restrict__ AT = g_S[2 * g + 1];   // AT[k*256+m] = S2[m][k]
    float* Wr = g_Wr[g]; float* Wi = g_Wi[g]; float* Wn = g_Wn[g];

    // stage 32 columns of S1 as B
    for (int idx = tid; idx < NS * NT; idx += 256) {
        int k = idx & 255, b = idx >> 8;
        sPsi[k * NTP + b] = S1[(cbase + b) * NS + k];
    }
    float2 pre[8];
    #pragma unroll
    for (int r = 0; r < 8; r++) pre[r] = AT[tid + r * 256];
    __syncthreads();

    int mh = warp >> 2, bo = warp & 3;
    int mbase = mh * 128 + lane * 4;
    ull acc[4][8];
    #pragma unroll
    for (int r = 0; r < 4; r++)
        #pragma unroll
        for (int j = 0; j < 8; j++) acc[r][j] = 0ull;

    for (int kc = 0; kc < 32; kc++) {
        float2* buf = sA2 + (kc & 1) * 2048;
        #pragma unroll
        for (int r = 0; r < 8; r++) buf[tid + r * 256] = pre[r];
        if (kc + 1 < 32) {
            #pragma unroll
            for (int r = 0; r < 8; r++) pre[r] = AT[(kc + 1) * 2048 + tid + r * 256];
        }
        __syncthreads();
        #pragma unroll
        for (int kk = 0; kk < 8; kk++) {
            int k = kc * 8 + kk;
            float4 a01 = *reinterpret_cast<const float4*>(&buf[kk * 256 + mbase]);
            float4 a23 = *reinterpret_cast<const float4*>(&buf[kk * 256 + mbase + 2]);
            ull ap[4], as_[4];
            ap[0] = pack2(a01.x, a01.y); as_[0] = pack2(a01.y, a01.x);
            ap[1] = pack2(a01.z, a01.w); as_[1] = pack2(a01.w, a01.z);
            ap[2] = pack2(a23.x, a23.y); as_[2] = pack2(a23.y, a23.x);
            ap[3] = pack2(a23.z, a23.w); as_[3] = pack2(a23.w, a23.z);
            #pragma unroll
            for (int j = 0; j < 8; j++) {
                float2 bv = sPsi[k * NTP + bo * 8 + j];
                ull Br = pack2(bv.x, bv.x);
                ull Bn = pack2(-bv.y, bv.y);
                #pragma unroll
                for (int r = 0; r < 4; r++) {
                    ffma2(acc[r][j], ap[r], Br);
                    ffma2(acc[r][j], as_[r], Bn);
                }
            }
        }
        __syncthreads();
    }
    // write planes: column c -> W*[c*256 + m]
    #pragma unroll
    for (int j = 0; j < 8; j++) {
        int c = cbase + bo * 8 + j;
        float4 vr, vi, vn;
        float2 e0 = unpack2(acc[0][j]), e1 = unpack2(acc[1][j]);
        float2 e2 = unpack2(acc[2][j]), e3 = unpack2(acc[3][j]);
        vr = make_float4(e0.x, e1.x, e2.x, e3.x);
        vi = make_float4(e0.y, e1.y, e2.y, e3.y);
        vn = make_float4(-e0.y, -e1.y, -e2.y, -e3.y);
        *reinterpret_cast<float4*>(&Wr[c * NS + mbase]) = vr;
        *reinterpret_cast<float4*>(&Wi[c * NS + mbase]) = vi;
        *reinterpret_cast<float4*>(&Wn[c * NS + mbase]) = vn;
    }
}

// ---------------- K2: fused per-batch pipeline ----------------
__device__ __forceinline__ void su2_mul(float& Eur, float& Eui, float& Evr, float& Evi,
                                        float gur, float gui, float gvr, float gvi) {
    float ur = gur * Eur - gui * Eui - (gvr * Evr + gvi * Evi);
    float ui = gur * Eui + gui * Eur - (gvr * Evi - gvi * Evr);
    float vr = gvr * Eur - gvi * Eui + (gur * Evr + gui * Evi);
    float vi = gvr * Eui + gvi * Eur + (gur * Evi - gui * Evr);
    Eur = ur; Eui = ui; Evr = vr; Evi = vi;
}

__device__ __forceinline__ float4 compose_E(const float* __restrict__ x, int bg,
                                            int xoff, int enc, int i) {
    float Eur = 1.f, Eui = 0.f, Evr = 0.f, Evi = 0.f;
    #pragma unroll
    for (int j = 0; j < 4; j++) {
        float2 p0 = g_encphi[enc * 64 + 8 * i + 2 * j];
        float2 p1 = g_encphi[enc * 64 + 8 * i + 2 * j + 1];
        float xv = x[(size_t)bg * NXF + xoff + 4 * i + j];
        float sx, cx;
        sincosf(0.5f * xv, &sx, &cx);
        if ((j & 1) == 0) {
            su2_mul(Eur, Eui, Evr, Evi, p0.x, 0.f, p0.y, 0.f);   // RY(p0)
            su2_mul(Eur, Eui, Evr, Evi, cx, 0.f, 0.f, -sx);      // RX(x)
            su2_mul(Eur, Eui, Evr, Evi, p1.x, 0.f, p1.y, 0.f);   // RY(p1)
        } else {
            su2_mul(Eur, Eui, Evr, Evi, p0.x, 0.f, 0.f, -p0.y);  // RX(p0)
            su2_mul(Eur, Eui, Evr, Evi, cx, 0.f, sx, 0.f);       // RY(x)
            su2_mul(Eur, Eui, Evr, Evi, p1.x, 0.f, 0.f, -p1.y);  // RX(p1)
        }
    }
    return make_float4(Eur, Eui, Evr, Evi);
}

__device__ __forceinline__ void apply_gates(float2* sPsi, const float4* sE, int tid) {
    #pragma unroll
    for (int q = 0; q < 8; q++) {
        int p = 7 - q;
        int low = (1 << p) - 1;
        #pragma unroll
        for (int it = 0; it < (128 * NT) / 256; it++) {  // 16
            int task = tid + it * 256;
            int b = task & (NT - 1);
            int pr = task >> 5;
            int n0 = ((pr & ~low) << 1) | (pr & low);
            int n1 = n0 | (1 << p);
            float4 E = sE[q * NT + b];
            float2 a0 = sPsi[n0 * NTP + b];
            float2 a1 = sPsi[n1 * NTP + b];
            float2 b0, b1;
            b0.x = E.x * a0.x - E.y * a0.y - (E.z * a1.x + E.w * a1.y);
            b0.y = E.x * a0.y + E.y * a0.x - (E.z * a1.y - E.w * a1.x);
            b1.x = E.z * a0.x - E.w * a0.y + (E.x * a1.x + E.y * a1.y);
            b1.y = E.z * a0.y + E.w * a0.x + (E.x * a1.y - E.y * a1.x);
            sPsi[n0 * NTP + b] = b0;
            sPsi[n1 * NTP + b] = b1;
        }
        __syncthreads();
    }
}

// plane-based in-place complex GEMM: sPsi[m][b] = sum_k U'[m][k] * sPsi[k][b]
// A from re/im/-im float planes (3 LDS.128, zero MOVs); B pre-splatted in sB.
__device__ __forceinline__ void gemm_planes(float2* sPsi, float* sAr, float* sAi, float* sAn,
                                            float4* sB,
                                            const float* __restrict__ Wr,
                                            const float* __restrict__ Wi,
                                            const float* __restrict__ Wn,
                                            float4 pR[2], float4 pI[2], float4 pN[2],
                                            int tid, int lane, int warp) {
    int mh = warp >> 2, bo = warp & 3;
    int mbase = mh * 128 + lane * 4;
    ull aR[2][8], aI[2][8];
    #pragma unroll
    for (int p = 0; p < 2; p++)
        #pragma unroll
        for (int j = 0; j < 8; j++) { aR[p][j] = 0ull; aI[p][j] = 0ull; }

    for (int kc = 0; kc < 32; kc++) {
        __syncthreads();   // previous compute done reading sA*/sB
        *reinterpret_cast<float4*>(&sAr[tid * 8])     = pR[0];
        *reinterpret_cast<float4*>(&sAr[tid * 8 + 4]) = pR[1];
        *reinterpret_cast<float4*>(&sAi[tid * 8])     = pI[0];
        *reinterpret_cast<float4*>(&sAi[tid * 8 + 4]) = pI[1];
        *reinterpret_cast<float4*>(&sAn[tid * 8])     = pN[0];
        *reinterpret_cast<float4*>(&sAn[tid * 8 + 4]) = pN[1];
        {
            int kk = tid >> 5, b = tid & 31;
            float2 bv = sPsi[(kc * 8 + kk) * NTP + b];
            sB[tid] = make_float4(bv.x, bv.x, bv.y, bv.y);
        }
        __syncthreads();
        if (kc + 1 < 32) {
            pR[0] = *reinterpret_cast<const float4*>(&Wr[(kc + 1) * 2048 + tid * 8]);
            pR[1] = *reinterpret_cast<const float4*>(&Wr[(kc + 1) * 2048 + tid * 8 + 4]);
            pI[0] = *reinterpret_cast<const float4*>(&Wi[(kc + 1) * 2048 + tid * 8]);
            pI[1] = *reinterpret_cast<const float4*>(&Wi[(kc + 1) * 2048 + tid * 8 + 4]);
            pN[0] = *reinterpret_cast<const float4*>(&Wn[(kc + 1) * 2048 + tid * 8]);
            pN[1] = *reinterpret_cast<const float4*>(&Wn[(kc + 1) * 2048 + tid * 8 + 4]);
        }
        #pragma unroll
        for (int kk = 0; kk < 8; kk++) {
            ulonglong2 Ar = *reinterpret_cast<const ulonglong2*>(&sAr[kk * 256 + mbase]);
            ulonglong2 Ai = *reinterpret_cast<const ulonglong2*>(&sAi[kk * 256 + mbase]);
            ulonglong2 An = *reinterpret_cast<const ulonglong2*>(&sAn[kk * 256 + mbase]);
            #pragma unroll
            for (int j = 0; j < 8; j++) {
                ulonglong2 B = *reinterpret_cast<const ulonglong2*>(&sB[kk * 32 + bo * 8 + j]);
                ffma2(aR[0][j], Ar.x, B.x); ffma2(aR[0][j], An.x, B.y);
                ffma2(aR[1][j], Ar.y, B.x); ffma2(aR[1][j], An.y, B.y);
                ffma2(aI[0][j], Ar.x, B.y); ffma2(aI[0][j], Ai.x, B.x);
                ffma2(aI[1][j], Ar.y, B.y); ffma2(aI[1][j], Ai.y, B.x);
            }
        }
    }
    __syncthreads();  // all reads of sPsi done before overwrite
    #pragma unroll
    for (int p = 0; p < 2; p++)
        #pragma unroll
        for (int j = 0; j < 8; j++) {
            float2 re = unpack2(aR[p][j]);
            float2 im = unpack2(aI[p][j]);
            int m0 = mbase + 2 * p;
            int b = bo * 8 + j;
            sPsi[m0 * NTP + b]       = make_float2(re.x, im.x);
            sPsi[(m0 + 1) * NTP + b] = make_float2(re.y, im.y);
        }
    __syncthreads();
}

__global__ void __launch_bounds__(256, 2) k_main(const float* __restrict__ x,
                                                 float* __restrict__ out) {
    extern __shared__ float smraw[];
    float2* sPsi = (float2*)smraw;                    // NS*NTP float2   (67584 B)
    float*  sAr  = (float*)(sPsi + NS * NTP);         // 2048 f          ( 8192 B)
    float*  sAi  = sAr + 2048;                        // 2048 f
    float*  sAn  = sAi + 2048;                        // 2048 f
    float4* sB   = (float4*)(sAn + 2048);             // 256 f4          ( 4096 B)
    float4* sE   = sB + 256;                          // 256 f4          ( 4096 B)

    int tid = threadIdx.x;
    int lane = tid & 31, warp = tid >> 5;
    int bbase = blockIdx.x * NT;

    // ---- prefetch first A-chunk of U2' planes (hidden behind encode compute) ----
    float4 pR[2], pI[2], pN[2];
    pR[0] = *reinterpret_cast<const float4*>(&g_Wr[0][tid * 8]);
    pR[1] = *reinterpret_cast<const float4*>(&g_Wr[0][tid * 8 + 4]);
    pI[0] = *reinterpret_cast<const float4*>(&g_Wi[0][tid * 8]);
    pI[1] = *reinterpret_cast<const float4*>(&g_Wi[0][tid * 8 + 4]);
    pN[0] = *reinterpret_cast<const float4*>(&g_Wn[0][tid * 8]);
    pN[1] = *reinterpret_cast<const float4*>(&g_Wn[0][tid * 8 + 4]);

    // ---- E1 compose ----
    {
        int b = tid & (NT - 1), i = tid >> 5;
        sE[i * NT + b] = compose_E(x, bbase + b, 0, 0, i);
    }
    // ---- init Psi = v0 ----
    for (int idx = tid; idx < NS * NT; idx += 256) {
        int b = idx & (NT - 1), amp = idx >> 5;
        sPsi[amp * NTP + b] = g_v0[amp];
    }
    __syncthreads();

    apply_gates(sPsi, sE, tid);
    gemm_planes(sPsi, sAr, sAi, sAn, sB, g_Wr[0], g_Wi[0], g_Wn[0], pR, pI, pN, tid, lane, warp);

    // ---- prefetch U3' chunk 0, then E2 compose ----
    pR[0] = *reinterpret_cast<const float4*>(&g_Wr[1][tid * 8]);
    pR[1] = *reinterpret_cast<const float4*>(&g_Wr[1][tid * 8 + 4]);
    pI[0] = *reinterpret_cast<const float4*>(&g_Wi[1][tid * 8]);
    pI[1] = *reinterpret_cast<const float4*>(&g_Wi[1][tid * 8 + 4]);
    pN[0] = *reinterpret_cast<const float4*>(&g_Wn[1][tid * 8]);
    pN[1] = *reinterpret_cast<const float4*>(&g_Wn[1][tid * 8 + 4]);
    {
        int b = tid & (NT - 1), i = tid >> 5;
        sE[i * NT + b] = compose_E(x, bbase + b, 32, 1, i);
    }
    __syncthreads();

    apply_gates(sPsi, sE, tid);
    gemm_planes(sPsi, sAr, sAi, sAn, sB, g_Wr[1], g_Wi[1], g_Wn[1], pR, pI, pN, tid, lane, warp);

    // ---- measurement: warp w handles batches w*4..w*4+3 ----
    for (int j = 0; j < 4; j++) {
        int b = warp * 4 + j;
        float sums[8];
        #pragma unroll
        for (int k = 0; k < 8; k++) sums[k] = 0.f;
        #pragma unroll
        for (int r = 0; r < 8; r++) {
            int m = lane + 32 * r;
            float2 ps = sPsi[m * NTP + b];
            float p2 = ps.x * ps.x + ps.y * ps.y;
            sums[4] += (m & 128) ? -p2 : p2;   // Z q0
            sums[5] += (m & 64)  ? -p2 : p2;   // Z q1
            sums[6] += (m & 32)  ? -p2 : p2;   // Z q2
            sums[7] += (m & 16)  ? -p2 : p2;   // Z q3
            float2 q0 = sPsi[(m ^ 128) * NTP + b];
            sums[0] += ps.x * q0.x + ps.y * q0.y;   // X q0
            float2 q1 = sPsi[(m ^ 64) * NTP + b];
            sums[1] += ps.x * q1.x + ps.y * q1.y;   // X q1
            float2 q2 = sPsi[(m ^ 32) * NTP + b];
            sums[2] += ps.x * q2.x + ps.y * q2.y;   // X q2
            float2 q3 = sPsi[(m ^ 16) * NTP + b];
            sums[3] += ps.x * q3.x + ps.y * q3.y;   // X q3
        }
        #pragma unroll
        for (int off = 16; off; off >>= 1) {
            #pragma unroll
            for (int k = 0; k < 8; k++)
                sums[k] += __shfl_xor_sync(0xffffffffu, sums[k], off);
        }
        if (lane < 8) out[(size_t)(bbase + b) * 8 + lane] = sums[lane];
    }
}

// ---------------- launch ----------------
extern "C" void kernel_launch(void* const* d_in, const int* in_sizes, int n_in,
                              void* d_out, int out_size) {
    const float* x   = (const float*)d_in[0];
    const float* phi = (const float*)d_in[1];
    float* out = (float*)d_out;

    const size_t smem_c = (size_t)(NS * NTP) * sizeof(float2)   // 67584
                        + (size_t)(2 * 2048) * sizeof(float2);  // 32768
    const size_t smem_m = (size_t)(NS * NTP) * sizeof(float2)   // 67584
                        + 3 * 2048 * sizeof(float)              // 24576
                        + 256 * sizeof(float4)                  //  4096
                        + 256 * sizeof(float4);                 //  4096
    cudaFuncSetAttribute(k_comb, cudaFuncAttributeMaxDynamicSharedMemorySize, (int)smem_c);
    cudaFuncSetAttribute(k_main, cudaFuncAttributeMaxDynamicSharedMemorySize, (int)smem_m);

    k_tables<<<20, 256>>>(phi);
    k_build<<<129, 256>>>();
    k_comb<<<16, 256, smem_c>>>();
    k_main<<<NBLK, 256, smem_m>>>(x, out);
}

// round 8
// speedup vs baseline: 1.1609x; 1.1609x over previous
#include <cuda_runtime.h>
#include <math.h>

#define NQ 8
#define NS 256          // 2^8 amplitudes
#define DEPTH 200
#define BSZ 16384
#define NXF 64
#define NT 32           // batches per block in main kernel
#define NTP 33          // padded batch stride in shared
#define NBLK (BSZ/NT)   // 512 blocks

typedef unsigned long long ull;

// ---------------- device globals (no cudaMalloc allowed) ----------------
__device__ float4 g_uv[600 * 8];     // per layer/qubit: (u.re,u.im,v.re,v.im) of RY(b)*RX(a)
__device__ float2 g_encphi[128];     // (cos(phi/2), sin(phi/2)) for encode phi angles
__device__ float2 g_v0[NS];          // U1 |0>
__device__ float2 g_S[4][NS * NS];   // segment columns: [s][c*256+m]; s:0=U2s1,1=U2s2,2=U3s1,3=U3s2
__device__ float2 g_WT[2][NS * NS];  // U'[m][k] stored [k*256+m]  (0=U2', 1=U3')

// ---------------- packed f32x2 helpers ----------------
__device__ __forceinline__ void ffma2(ull& d, ull a, ull b) {
    asm("fma.rn.f32x2 %0, %1, %2, %0;" : "+l"(d) : "l"(a), "l"(b));
}
__device__ __forceinline__ ull pack2(float lo, float hi) {
    ull r; asm("mov.b64 %0, {%1, %2};" : "=l"(r) : "f"(lo), "f"(hi)); return r;
}
__device__ __forceinline__ float2 unpack2(ull v) {
    float2 r; asm("mov.b64 {%0, %1}, %2;" : "=f"(r.x), "=f"(r.y) : "l"(v)); return r;
}

// ring-CZ parity sign for amplitude index n (qubit i <-> bit 7-i)
__device__ __forceinline__ float czsign(int n) {
    int par = __popc(n & (n >> 1)) + ((n & (n >> 7)) & 1);
    return (par & 1) ? -1.0f : 1.0f;
}

// ---------------- K0: angle tables ----------------
__global__ void k_tables(const float* __restrict__ phi) {
    int tid = blockIdx.x * blockDim.x + threadIdx.x;
    int stride = gridDim.x * blockDim.x;
    for (int idx = tid; idx < 600 * 8; idx += stride) {
        int L = idx >> 3, q = idx & 7;
        int base, l;
        if (L < 200)      { base = 0;    l = L; }
        else if (L < 400) { base = 3264; l = L - 200; }
        else              { base = 6528; l = L - 400; }
        float a = phi[base + l * 16 + q];
        float b = phi[base + l * 16 + 8 + q];
        float ca, sa, cb, sb;
        sincosf(0.5f * a, &sa, &ca);
        sincosf(0.5f * b, &sb, &cb);
        g_uv[idx] = make_float4(ca * cb, sa * sb, ca * sb, -sa * cb);
    }
    for (int idx = tid; idx < 128; idx += stride) {
        int base = (idx < 64) ? 3200 : 6400;
        float p = phi[base + idx];
        float c, s;
        sincosf(0.5f * p, &s, &c);
        g_encphi[idx] = make_float2(c, s);
    }
}

// ---------------- segment layer step (register/shuffle state machine) ----------------
__device__ __forceinline__ void seg_step(float2 amp[8], const float4 uvL[8],
                                         const float sgn[8], int lane, bool docz) {
    // lane-bit gates: q = 0..4  (amp bit p = 7-q lives in lane bit p-3)
    #pragma unroll
    for (int q = 0; q < 5; q++) {
        float4 uv = uvL[q];
        int b = 4 - q;
        int mybit = (lane >> b) & 1;
        float mai = mybit ? -uv.y : uv.y;
        float mbr = mybit ?  uv.z : -uv.z;
        ull Ap = pack2(uv.x, mai),  An = pack2(-mai, uv.x);
        ull Bp = pack2(mbr, uv.w),  Bn = pack2(-uv.w, mbr);
        #pragma unroll
        for (int j = 0; j < 8; j++) {
            float pr = __shfl_xor_sync(0xffffffffu, amp[j].x, 1 << b);
            float pi = __shfl_xor_sync(0xffffffffu, amp[j].y, 1 << b);
            ull acc = 0ull;
            ffma2(acc, pack2(amp[j].x, amp[j].x), Ap);
            ffma2(acc, pack2(amp[j].y, amp[j].y), An);
            ffma2(acc, pack2(pr, pr), Bp);
            ffma2(acc, pack2(pi, pi), Bn);
            amp[j] = unpack2(acc);
        }
    }
    // local gates: q = 5,6,7 (bit p = 2,1,0 within the 8 local amps)
    #pragma unroll
    for (int q = 5; q < 8; q++) {
        float4 uv = uvL[q];
        int p = 7 - q;
        ull A00p = pack2( uv.x,  uv.y), A00n = pack2(-uv.y,  uv.x);
        ull A01p = pack2(-uv.z,  uv.w), A01n = pack2(-uv.w, -uv.z);
        ull A10p = pack2( uv.z,  uv.w), A10n = pack2(-uv.w,  uv.z);
        ull A11p = pack2( uv.x, -uv.y), A11n = pack2( uv.y,  uv.x);
        #pragma unroll
        for (int t = 0; t < 4; t++) {
            int lowm = (1 << p) - 1;
            int j0 = ((t & ~lowm) << 1) | (t & lowm);
            int j1 = j0 | (1 << p);
            float2 a0 = amp[j0], a1 = amp[j1];
            ull sx0 = pack2(a0.x, a0.x), sy0 = pack2(a0.y, a0.y);
            ull sx1 = pack2(a1.x, a1.x), sy1 = pack2(a1.y, a1.y);
            ull acc0 = 0ull, acc1 = 0ull;
            ffma2(acc0, sx0, A00p); ffma2(acc0, sy0, A00n);
            ffma2(acc0, sx1, A01p); ffma2(acc0, sy1, A01n);
            ffma2(acc1, sx0, A10p); ffma2(acc1, sy0, A10n);
            ffma2(acc1, sx1, A11p); ffma2(acc1, sy1, A11n);
            amp[j0] = unpack2(acc0);
            amp[j1] = unpack2(acc1);
        }
    }
    if (docz) {
        #pragma unroll
        for (int j = 0; j < 8; j++) { amp[j].x *= sgn[j]; amp[j].y *= sgn[j]; }
    }
}

// ---------------- K1: build segment columns + v0 ----------------
// warps 0..1023: segment s = gw>>8 (100 layers each), column gw&255.
// warp 1024: v0 over full 200 layers of block 1.
__global__ void __launch_bounds__(256) k_build() {
    int gw = blockIdx.x * 8 + (threadIdx.x >> 5);
    if (gw >= 1025) return;
    int lane = threadIdx.x & 31;

    int Lbase, NL, col;
    bool czlast;
    float2* outp;
    float initv;
    if (gw < 1024) {
        int s = gw >> 8;
        col = gw & 255;
        Lbase = 200 + s * 100;        // s=0:200, 1:300, 2:400, 3:500
        NL = 100;
        czlast = (s != 3);            // only U3-seg2's final layer has no CZ
        outp = &g_S[s][col * NS];
        initv = (s == 0 || s == 2) ? czsign(col) : 1.0f;  // fold encode-Dcz into seg1 init
    } else {
        Lbase = 0; NL = DEPTH; czlast = true; col = 0; outp = g_v0; initv = 1.0f;
    }

    float2 amp[8];
    float  sgn[8];
    #pragma unroll
    for (int j = 0; j < 8; j++) {
        int n = lane * 8 + j;
        amp[j] = (n == col) ? make_float2(initv, 0.f) : make_float2(0.f, 0.f);
        sgn[j] = czsign(n);
    }

    float4 uvA[8], uvB[8];
    #pragma unroll
    for (int q = 0; q < 8; q++) uvA[q] = g_uv[Lbase * 8 + q];

    for (int l = 0; l < NL; l += 2) {
        #pragma unroll
        for (int q = 0; q < 8; q++) uvB[q] = g_uv[(Lbase + l + 1) * 8 + q];
        seg_step(amp, uvA, sgn, lane, (l < NL - 1) || czlast);
        if (l + 2 < NL) {
            #pragma unroll
            for (int q = 0; q < 8; q++) uvA[q] = g_uv[(Lbase + l + 2) * 8 + q];
        }
        seg_step(amp, uvB, sgn, lane, (l + 1 < NL - 1) || czlast);
    }

    float4* o4 = reinterpret_cast<float4*>(outp);
    #pragma unroll
    for (int jj = 0; jj < 4; jj++)
        o4[lane * 4 + jj] = make_float4(amp[2 * jj].x, amp[2 * jj].y,
                                        amp[2 * jj + 1].x, amp[2 * jj + 1].y);
}

// ---------------- K1b: combine segments  U' = S2 * S1 -> g_WT [k][m] complex ----------------
// block (g, cb): computes columns cb*32..+31 of U'(g).
__global__ void __launch_bounds__(256) k_comb() {
    extern __shared__ float smraw[];
    float2* sPsi = (float2*)smraw;            // NS * NTP
    float2* sA2  = sPsi + NS * NTP;           // 2 x 2048 ping-pong

    int tid = threadIdx.x, lane = tid & 31, warp = tid >> 5;
    int g = blockIdx.x >> 3;
    int cbase = (blockIdx.x & 7) * 32;
    const float2* __restrict__ S1 = g_S[2 * g];
    const float2* __restrict__ AT = g_S[2 * g + 1];   // AT[k*256+m] = S2[m][k]
    float2* W = g_WT[g];

    // stage 32 columns of S1 as B
    for (int idx = tid; idx < NS * NT; idx += 256) {
        int k = idx & 255, b = idx >> 8;
        sPsi[k * NTP + b] = S1[(cbase + b) * NS + k];
    }
    float2 pre[8];
    #pragma unroll
    for (int r = 0; r < 8; r++) pre[r] = AT[tid + r * 256];
    __syncthreads();

    int mh = warp >> 2, bo = warp & 3;
    int mbase = mh * 128 + lane * 4;
    ull acc[4][8];
    #pragma unroll
    for (int r = 0; r < 4; r++)
        #pragma unroll
        for (int j = 0; j < 8; j++) acc[r][j] = 0ull;

    for (int kc = 0; kc < 32; kc++) {
        float2* buf = sA2 + (kc & 1) * 2048;
        #pragma unroll
        for (int r = 0; r < 8; r++) buf[tid + r * 256] = pre[r];
        if (kc + 1 < 32) {
            #pragma unroll
            for (int r = 0; r < 8; r++) pre[r] = AT[(kc + 1) * 2048 + tid + r * 256];
        }
        __syncthreads();
        #pragma unroll
        for (int kk = 0; kk < 8; kk++) {
            int k = kc * 8 + kk;
            float4 a01 = *reinterpret_cast<const float4*>(&buf[kk * 256 + mbase]);
            float4 a23 = *reinterpret_cast<const float4*>(&buf[kk * 256 + mbase + 2]);
            ull ap[4], as_[4];
            ap[0] = pack2(a01.x, a01.y); as_[0] = pack2(a01.y, a01.x);
            ap[1] = pack2(a01.z, a01.w); as_[1] = pack2(a01.w, a01.z);
            ap[2] = pack2(a23.x, a23.y); as_[2] = pack2(a23.y, a23.x);
            ap[3] = pack2(a23.z, a23.w); as_[3] = pack2(a23.w, a23.z);
            #pragma unroll
            for (int j = 0; j < 8; j++) {
                float2 bv = sPsi[k * NTP + bo * 8 + j];
                ull Br = pack2(bv.x, bv.x);
                ull Bn = pack2(-bv.y, bv.y);
                #pragma unroll
                for (int r = 0; r < 4; r++) {
                    ffma2(acc[r][j], ap[r], Br);
                    ffma2(acc[r][j], as_[r], Bn);
                }
            }
        }
        __syncthreads();
    }
    // write column c -> W[c*256 + m] (c is the k-index of the [k][m] layout)
    #pragma unroll
    for (int j = 0; j < 8; j++) {
        int c = cbase + bo * 8 + j;
        float2 e0 = unpack2(acc[0][j]), e1 = unpack2(acc[1][j]);
        float2 e2 = unpack2(acc[2][j]), e3 = unpack2(acc[3][j]);
        *reinterpret_cast<float4*>(&W[c * NS + mbase])     = make_float4(e0.x, e0.y, e1.x, e1.y);
        *reinterpret_cast<float4*>(&W[c * NS + mbase + 2]) = make_float4(e2.x, e2.y, e3.x, e3.y);
    }
}

// ---------------- K2: fused per-batch pipeline ----------------
__device__ __forceinline__ void su2_mul(float& Eur, float& Eui, float& Evr, float& Evi,
                                        float gur, float gui, float gvr, float gvi) {
    float ur = gur * Eur - gui * Eui - (gvr * Evr + gvi * Evi);
    float ui = gur * Eui + gui * Eur - (gvr * Evi - gvi * Evr);
    float vr = gvr * Eur - gvi * Eui + (gur * Evr + gui * Evi);
    float vi = gvr * Eui + gvi * Eur + (gur * Evi - gui * Evr);
    Eur = ur; Eui = ui; Evr = vr; Evi = vi;
}

__device__ __forceinline__ float4 compose_E(const float* __restrict__ x, int bg,
                                            int xoff, int enc, int i) {
    float Eur = 1.f, Eui = 0.f, Evr = 0.f, Evi = 0.f;
    #pragma unroll
    for (int j = 0; j < 4; j++) {
        float2 p0 = g_encphi[enc * 64 + 8 * i + 2 * j];
        float2 p1 = g_encphi[enc * 64 + 8 * i + 2 * j + 1];
        float xv = x[(size_t)bg * NXF + xoff + 4 * i + j];
        float sx, cx;
        sincosf(0.5f * xv, &sx, &cx);
        if ((j & 1) == 0) {
            su2_mul(Eur, Eui, Evr, Evi, p0.x, 0.f, p0.y, 0.f);   // RY(p0)
            su2_mul(Eur, Eui, Evr, Evi, cx, 0.f, 0.f, -sx);      // RX(x)
            su2_mul(Eur, Eui, Evr, Evi, p1.x, 0.f, p1.y, 0.f);   // RY(p1)
        } else {
            su2_mul(Eur, Eui, Evr, Evi, p0.x, 0.f, 0.f, -p0.y);  // RX(p0)
            su2_mul(Eur, Eui, Evr, Evi, cx, 0.f, sx, 0.f);       // RY(x)
            su2_mul(Eur, Eui, Evr, Evi, p1.x, 0.f, 0.f, -p1.y);  // RX(p1)
        }
    }
    return make_float4(Eur, Eui, Evr, Evi);
}

__device__ __forceinline__ void apply_gates(float2* sPsi, const float4* sE, int tid) {
    #pragma unroll
    for (int q = 0; q < 8; q++) {
        int p = 7 - q;
        int low = (1 << p) - 1;
        #pragma unroll
        for (int it = 0; it < (128 * NT) / 256; it++) {  // 16
            int task = tid + it * 256;
            int b = task & (NT - 1);
            int pr = task >> 5;
            int n0 = ((pr & ~low) << 1) | (pr & low);
            int n1 = n0 | (1 << p);
            float4 E = sE[q * NT + b];
            float2 a0 = sPsi[n0 * NTP + b];
            float2 a1 = sPsi[n1 * NTP + b];
            float2 b0, b1;
            b0.x = E.x * a0.x - E.y * a0.y - (E.z * a1.x + E.w * a1.y);
            b0.y = E.x * a0.y + E.y * a0.x - (E.z * a1.y - E.w * a1.x);
            b1.x = E.z * a0.x - E.w * a0.y + (E.x * a1.x + E.y * a1.y);
            b1.y = E.z * a0.y + E.w * a0.x + (E.x * a1.y - E.y * a1.x);
            sPsi[n0 * NTP + b] = b0;
            sPsi[n1 * NTP + b] = b1;
        }
        __syncthreads();
    }
}

// in-place complex GEMM, packed f32x2 FMAs, ping-pong A staging (R5 version):
//   sPsi[m][b] = sum_k AT[k][m] * sPsi[k][b]
__device__ __forceinline__ void do_gemm(float2* sPsi, float2* sA2,
                                        const float2* __restrict__ AT,
                                        float2 pre[8],
                                        int tid, int lane, int warp) {
    int mh = warp >> 2;            // m-half:   m = mh*128 + lane*4 + rr
    int bo = warp & 3;             // b-octet:  b = bo*8 + j
    int mbase = mh * 128 + lane * 4;
    ull acc[4][8];
    #pragma unroll
    for (int r = 0; r < 4; r++)
        #pragma unroll
        for (int j = 0; j < 8; j++) acc[r][j] = 0ull;

    for (int kc = 0; kc < 32; kc++) {
        float2* buf = sA2 + (kc & 1) * 2048;
        #pragma unroll
        for (int r = 0; r < 8; r++) buf[tid + r * 256] = pre[r];
        if (kc + 1 < 32) {
            #pragma unroll
            for (int r = 0; r < 8; r++) pre[r] = AT[(kc + 1) * 2048 + tid + r * 256];
        }
        __syncthreads();
        #pragma unroll
        for (int kk = 0; kk < 8; kk++) {
            int k = kc * 8 + kk;
            float4 a01 = *reinterpret_cast<const float4*>(&buf[kk * 256 + mbase]);
            float4 a23 = *reinterpret_cast<const float4*>(&buf[kk * 256 + mbase + 2]);
            ull ap[4], as_[4];
            ap[0] = pack2(a01.x, a01.y); as_[0] = pack2(a01.y, a01.x);
            ap[1] = pack2(a01.z, a01.w); as_[1] = pack2(a01.w, a01.z);
            ap[2] = pack2(a23.x, a23.y); as_[2] = pack2(a23.y, a23.x);
            ap[3] = pack2(a23.z, a23.w); as_[3] = pack2(a23.w, a23.z);
            #pragma unroll
            for (int j = 0; j < 8; j++) {
                float2 bv = sPsi[k * NTP + bo * 8 + j];
                ull Br = pack2(bv.x, bv.x);
                ull Bn = pack2(-bv.y, bv.y);
                #pragma unroll
                for (int r = 0; r < 4; r++) {
                    ffma2(acc[r][j], ap[r], Br);    // (a.r, a.i) * (b.r, b.r)
                    ffma2(acc[r][j], as_[r], Bn);   // (a.i, a.r) * (-b.i, b.i)
                }
            }
        }
    }
    __syncthreads();  // all reads of sPsi done before overwrite
    #pragma unroll
    for (int r = 0; r < 4; r++)
        #pragma unroll
        for (int j = 0; j < 8; j++)
            *reinterpret_cast<ull*>(&sPsi[(mbase + r) * NTP + bo * 8 + j]) = acc[r][j];
    __syncthreads();
}

__global__ void __launch_bounds__(256, 2) k_main(const float* __restrict__ x,
                                                 float* __restrict__ out) {
    extern __shared__ float smraw[];
    float2* sPsi = (float2*)smraw;              // NS * NTP           (67584 B)
    float2* sA2  = sPsi + NS * NTP;             // 2 x 2048 float2    (32768 B)
    float4* sE   = (float4*)(sA2 + 2 * 2048);   // 8 * NT float4      ( 4096 B)

    int tid = threadIdx.x;
    int lane = tid & 31, warp = tid >> 5;       // 8 warps
    int bbase = blockIdx.x * NT;

    // ---- prefetch first A-chunk of U2' (hidden behind encode compute) ----
    float2 pre[8];
    #pragma unroll
    for (int r = 0; r < 8; r++) pre[r] = g_WT[0][tid + r * 256];

    // ---- E1 compose: tid -> (b = tid&31, i = tid>>5) ----
    {
        int b = tid & (NT - 1), i = tid >> 5;
        sE[i * NT + b] = compose_E(x, bbase + b, 0, 0, i);
    }
    // ---- init Psi = v0 (broadcast over batches) ----
    for (int idx = tid; idx < NS * NT; idx += 256) {
        int b = idx & (NT - 1), amp = idx >> 5;
        sPsi[amp * NTP + b] = g_v0[amp];
    }
    __syncthreads();

    apply_gates(sPsi, sE, tid);                 // encode 1 (CZ folded into U2')
    do_gemm(sPsi, sA2, g_WT[0], pre, tid, lane, warp);

    // ---- prefetch first A-chunk of U3', then E2 compose ----
    #pragma unroll
    for (int r = 0; r < 8; r++) pre[r] = g_WT[1][tid + r * 256];
    {
        int b = tid & (NT - 1), i = tid >> 5;
        sE[i * NT + b] = compose_E(x, bbase + b, 32, 1, i);
    }
    __syncthreads();

    apply_gates(sPsi, sE, tid);                 // encode 2 (CZ folded into U3')
    do_gemm(sPsi, sA2, g_WT[1], pre, tid, lane, warp);

    // ---- measurement: warp w handles batches w*4..w*4+3 ----
    for (int j = 0; j < 4; j++) {
        int b = warp * 4 + j;
        float sums[8];
        #pragma unroll
        for (int k = 0; k < 8; k++) sums[k] = 0.f;
        #pragma unroll
        for (int r = 0; r < 8; r++) {
            int m = lane + 32 * r;
            float2 ps = sPsi[m * NTP + b];
            float p2 = ps.x * ps.x + ps.y * ps.y;
            sums[4] += (m & 128) ? -p2 : p2;   // Z q0
            sums[5] += (m & 64)  ? -p2 : p2;   // Z q1
            sums[6] += (m & 32)  ? -p2 : p2;   // Z q2
            sums[7] += (m & 16)  ? -p2 : p2;   // Z q3
            float2 q0 = sPsi[(m ^ 128) * NTP + b];
            sums[0] += ps.x * q0.x + ps.y * q0.y;   // X q0
            float2 q1 = sPsi[(m ^ 64) * NTP + b];
            sums[1] += ps.x * q1.x + ps.y * q1.y;   // X q1
            float2 q2 = sPsi[(m ^ 32) * NTP + b];
            sums[2] += ps.x * q2.x + ps.y * q2.y;   // X q2
            float2 q3 = sPsi[(m ^ 16) * NTP + b];
            sums[3] += ps.x * q3.x + ps.y * q3.y;   // X q3
        }
        #pragma unroll
        for (int off = 16; off; off >>= 1) {
            #pragma unroll
            for (int k = 0; k < 8; k++)
                sums[k] += __shfl_xor_sync(0xffffffffu, sums[k], off);
        }
        if (lane < 8) out[(size_t)(bbase + b) * 8 + lane] = sums[lane];
    }
}

// ---------------- launch ----------------
extern "C" void kernel_launch(void* const* d_in, const int* in_sizes, int n_in,
                              void* d_out, int out_size) {
    const float* x   = (const float*)d_in[0];
    const float* phi = (const float*)d_in[1];
    float* out = (float*)d_out;

    const size_t smem_c = (size_t)(NS * NTP) * sizeof(float2)   // 67584
                        + (size_t)(2 * 2048) * sizeof(float2);  // 32768
    const size_t smem_m = (size_t)(NS * NTP) * sizeof(float2)   // 67584
                        + (size_t)(2 * 2048) * sizeof(float2)   // 32768
                        + (size_t)(8 * NT) * sizeof(float4);    //  4096
    cudaFuncSetAttribute(k_comb, cudaFuncAttributeMaxDynamicSharedMemorySize, (int)smem_c);
    cudaFuncSetAttribute(k_main, cudaFuncAttributeMaxDynamicSharedMemorySize, (int)smem_m);

    k_tables<<<20, 256>>>(phi);
    k_build<<<129, 256>>>();
    k_comb<<<16, 256, smem_c>>>();
    k_main<<<NBLK, 256, smem_m>>>(x, out);
}